// round 1
// baseline (speedup 1.0000x reference)
#include <cuda_runtime.h>
#include <cuda_bf16.h>

// LayerNorm over last dim W=256 for input (B=8, C=128, H=128, W=256) fp32,
// then per-channel affine: out = (x - mean)/sqrt(var+eps) * gain[c] + bias[c].
//
// One warp per row. Each lane holds 8 contiguous floats (2x float4).
// Single pass: load once, warp-reduce sum/sumsq, normalize, store once.

#define EPS 1e-8f
#define W_DIM 256
#define H_DIM 128
#define C_DIM 128

__global__ __launch_bounds__(256, 8)
void ln_warp_kernel(const float* __restrict__ inp,
                    const float* __restrict__ gain,
                    const float* __restrict__ bias,
                    float* __restrict__ out,
                    int n_rows)
{
    const int warp_in_block = threadIdx.x >> 5;
    const int lane = threadIdx.x & 31;
    const int row = blockIdx.x * 8 + warp_in_block;
    if (row >= n_rows) return;

    const float* row_in = inp + (size_t)row * W_DIM;
    float* row_out = out + (size_t)row * W_DIM;

    // 8 floats per lane, contiguous 32B per lane -> coalesced 128B per 4 lanes
    float4 v0 = reinterpret_cast<const float4*>(row_in)[lane * 2 + 0];
    float4 v1 = reinterpret_cast<const float4*>(row_in)[lane * 2 + 1];

    float s  = v0.x + v0.y + v0.z + v0.w + v1.x + v1.y + v1.z + v1.w;
    float ss = v0.x*v0.x + v0.y*v0.y + v0.z*v0.z + v0.w*v0.w
             + v1.x*v1.x + v1.y*v1.y + v1.z*v1.z + v1.w*v1.w;

    // warp reduce (sum, sumsq)
    #pragma unroll
    for (int off = 16; off > 0; off >>= 1) {
        s  += __shfl_xor_sync(0xFFFFFFFFu, s,  off);
        ss += __shfl_xor_sync(0xFFFFFFFFu, ss, off);
    }

    const float inv_w = 1.0f / (float)W_DIM;
    float mean = s * inv_w;
    float var  = ss * inv_w - mean * mean;
    float rstd = rsqrtf(var + EPS);

    // channel index: row = ((b*C + c)*H + h)  ->  c = (row / H) % C
    int c = (row >> 7) & (C_DIM - 1);   // H=128, C=128 are powers of two
    float g = __ldg(gain + c);
    float b = __ldg(bias + c);

    float scale = rstd * g;
    float shift = b - mean * rstd * g;

    v0.x = v0.x * scale + shift;
    v0.y = v0.y * scale + shift;
    v0.z = v0.z * scale + shift;
    v0.w = v0.w * scale + shift;
    v1.x = v1.x * scale + shift;
    v1.y = v1.y * scale + shift;
    v1.z = v1.z * scale + shift;
    v1.w = v1.w * scale + shift;

    reinterpret_cast<float4*>(row_out)[lane * 2 + 0] = v0;
    reinterpret_cast<float4*>(row_out)[lane * 2 + 1] = v1;
}

extern "C" void kernel_launch(void* const* d_in, const int* in_sizes, int n_in,
                              void* d_out, int out_size) {
    const float* inp  = (const float*)d_in[0];
    const float* gain = (const float*)d_in[1];
    const float* bias = (const float*)d_in[2];
    float* out = (float*)d_out;

    int n_rows = in_sizes[0] / W_DIM;   // 8*128*128 = 131072
    int blocks = (n_rows + 7) / 8;      // 8 warps (rows) per block

    ln_warp_kernel<<<blocks, 256>>>(inp, gain, bias, out, n_rows);
}